// round 1
// baseline (speedup 1.0000x reference)
#include <cuda_runtime.h>
#include <cuda_bf16.h>

// Conv2d 3x3, stride 1, pad 1.
// x: [256, 224, 224] fp32 (batch 1 squeezed), w: [256, 256, 3, 3] fp32
// out: [256, 224, 224] fp32
//
// Strategy (round 0 baseline): register-blocked direct conv, FMA-pipe bound.
//  - weights pre-transposed to [ci][tap][co] in a __device__ scratch so a
//    32-co weight tile is a contiguous vectorizable row.
//  - block computes 32(W) x 8(H) x 32(co) outputs; thread computes 4px x 8co.
//  - ci processed in chunks of 4 with smem staging of input patch + weights.

#define C_IN   256
#define C_OUT  256
#define H_IMG  224
#define W_IMG  224

#define OW_T   32   // output tile width
#define OH_T   8    // output tile height
#define CO_T   32   // output channels per block
#define CI_C   4    // input channels per smem chunk

#define IW_T   34   // input patch width  (OW_T + 2)
#define IH_T   10   // input patch height (OH_T + 2)
#define IW_PAD 36   // padded row stride (multiple of 4 for float4 alignment)

// Transposed weights: [ci][tap(9)][co]  => 256*9*256 floats = 2.36 MB
__device__ float g_wt[C_IN * 9 * C_OUT];

__global__ void wt_transpose_kernel(const float* __restrict__ w) {
    int idx = blockIdx.x * blockDim.x + threadIdx.x;
    if (idx >= C_OUT * C_IN * 9) return;
    int co  = idx / (C_IN * 9);
    int rem = idx % (C_IN * 9);
    int ci  = rem / 9;
    int tap = rem % 9;
    g_wt[(ci * 9 + tap) * C_OUT + co] = w[idx];
}

__global__ __launch_bounds__(256, 2)
void conv3x3_kernel(const float* __restrict__ x, float* __restrict__ out) {
    __shared__ __align__(16) float s_in[CI_C][IH_T][IW_PAD];  // 5.76 KB
    __shared__ __align__(16) float s_w[CI_C][9][CO_T];        // 4.61 KB

    const int tid = threadIdx.x;
    const int bx = blockIdx.x;          // 0..6   (W tiles)
    const int by = blockIdx.y;          // 0..27  (H tiles)
    const int bz = blockIdx.z;          // 0..7   (co tiles)

    const int x0b = bx * OW_T;
    const int y0b = by * OH_T;
    const int co0 = bz * CO_T;

    const int tx  = tid & 7;            // 8 x-groups (4 px each)
    const int ty  = (tid >> 3) & 7;     // 8 rows
    const int tz  = tid >> 6;           // 4 co-groups (8 co each)
    const int tx4 = tx * 4;
    const int tz8 = tz * 8;

    float acc[8][4];
#pragma unroll
    for (int j = 0; j < 8; ++j)
#pragma unroll
        for (int p = 0; p < 4; ++p) acc[j][p] = 0.0f;

    for (int ci0 = 0; ci0 < C_IN; ci0 += CI_C) {
        __syncthreads();   // protect smem from previous iteration's readers

        // ---- stage input patch: CI_C planes of 34x10, zero-padded at borders
        for (int i = tid; i < CI_C * IH_T * IW_T; i += 256) {
            int c  = i / (IH_T * IW_T);
            int r  = i % (IH_T * IW_T);
            int yy = r / IW_T;
            int xx = r % IW_T;
            int gy = y0b + yy - 1;
            int gx = x0b + xx - 1;
            float v = 0.0f;
            if ((unsigned)gy < (unsigned)H_IMG && (unsigned)gx < (unsigned)W_IMG)
                v = x[((ci0 + c) * H_IMG + gy) * W_IMG + gx];
            s_in[c][yy][xx] = v;
        }
        // ---- stage weights: CI_C * 9 * 32 contiguous-co rows
        for (int i = tid; i < CI_C * 9 * CO_T; i += 256) {
            int c = i / (9 * CO_T);
            int r = i % (9 * CO_T);
            int t = r / CO_T;
            int j = r % CO_T;
            s_w[c][t][j] = g_wt[((ci0 + c) * 9 + t) * C_OUT + co0 + j];
        }
        __syncthreads();

        // ---- compute: pure register FFMA
#pragma unroll
        for (int c = 0; c < CI_C; ++c) {
#pragma unroll
            for (int ky = 0; ky < 3; ++ky) {
                const float* ir = &s_in[c][ty + ky][tx4];
                // 6 consecutive inputs -> 3 overlapping 4-wide windows
                float4 ia = *(const float4*)(ir);
                float2 ib = *(const float2*)(ir + 4);
                float iv[6] = {ia.x, ia.y, ia.z, ia.w, ib.x, ib.y};
#pragma unroll
                for (int kx = 0; kx < 3; ++kx) {
                    const float4* wv = (const float4*)&s_w[c][ky * 3 + kx][tz8];
                    float4 wA = wv[0];
                    float4 wB = wv[1];
                    float wr[8] = {wA.x, wA.y, wA.z, wA.w,
                                   wB.x, wB.y, wB.z, wB.w};
#pragma unroll
                    for (int j = 0; j < 8; ++j) {
#pragma unroll
                        for (int p = 0; p < 4; ++p) {
                            acc[j][p] += wr[j] * iv[kx + p];
                        }
                    }
                }
            }
        }
    }

    // ---- write 4px x 8co per thread, vectorized
    const int oy = y0b + ty;
    const int ox = x0b + tx4;
#pragma unroll
    for (int j = 0; j < 8; ++j) {
        int co = co0 + tz8 + j;
        float4 v = make_float4(acc[j][0], acc[j][1], acc[j][2], acc[j][3]);
        *(float4*)&out[(co * H_IMG + oy) * W_IMG + ox] = v;
    }
}

extern "C" void kernel_launch(void* const* d_in, const int* in_sizes, int n_in,
                              void* d_out, int out_size) {
    const float* x = (const float*)d_in[0];   // [1,256,224,224]
    const float* w = (const float*)d_in[1];   // [256,256,3,3]
    float* out = (float*)d_out;               // [256,224,224]

    (void)in_sizes; (void)n_in; (void)out_size;

    // 1) transpose weights into g_wt ([ci][tap][co])
    int nw = C_OUT * C_IN * 9;
    wt_transpose_kernel<<<(nw + 255) / 256, 256>>>(w);

    // 2) conv
    dim3 grid(W_IMG / OW_T, H_IMG / OH_T, C_OUT / CO_T);   // 7 x 28 x 8
    conv3x3_kernel<<<grid, 256>>>(x, out);
}